// round 7
// baseline (speedup 1.0000x reference)
#include <cuda_runtime.h>
#include <cuda_bf16.h>
#include <cstdint>

#define TSEQ 4096
#define DH   64
#define BS   128
#define NB   32
#define NH   16
#define NBH  32

// ---------------- low-level helpers (sm_100 base ISA only) ----------------
__device__ __forceinline__ uint32_t smem_u32(const void* p) {
    uint32_t a;
    asm("{ .reg .u64 t; cvta.to.shared.u64 t, %1; cvt.u32.u64 %0, t; }"
        : "=r"(a) : "l"(p));
    return a;
}
__device__ __forceinline__ void mma_bf16(float* d, const uint32_t* a, const uint32_t* b) {
    asm volatile(
        "mma.sync.aligned.m16n8k16.row.col.f32.bf16.bf16.f32 "
        "{%0,%1,%2,%3}, {%4,%5,%6,%7}, {%8,%9}, {%0,%1,%2,%3};"
        : "+f"(d[0]), "+f"(d[1]), "+f"(d[2]), "+f"(d[3])
        : "r"(a[0]), "r"(a[1]), "r"(a[2]), "r"(a[3]), "r"(b[0]), "r"(b[1]));
}
__device__ __forceinline__ void ldsm_x4(uint32_t* r, uint32_t addr) {
    asm volatile("ldmatrix.sync.aligned.m8n8.x4.shared.b16 {%0,%1,%2,%3}, [%4];"
                 : "=r"(r[0]), "=r"(r[1]), "=r"(r[2]), "=r"(r[3]) : "r"(addr));
}
__device__ __forceinline__ void ldsm_x4_t(uint32_t* r, uint32_t addr) {
    asm volatile("ldmatrix.sync.aligned.m8n8.x4.trans.shared.b16 {%0,%1,%2,%3}, [%4];"
                 : "=r"(r[0]), "=r"(r[1]), "=r"(r[2]), "=r"(r[3]) : "r"(addr));
}
#define SW128(x) ((x) ^ (((x) >> 3) & 0x70))

// split fp32 pair -> (hi bf16x2, lo bf16x2)
__device__ __forceinline__ void pksp(float x, float y, uint32_t& h, uint32_t& l) {
    unsigned short hx = __bfloat16_as_ushort(__float2bfloat16(x));
    unsigned short hy = __bfloat16_as_ushort(__float2bfloat16(y));
    float fx = __bfloat162float(__ushort_as_bfloat16(hx));
    float fy = __bfloat162float(__ushort_as_bfloat16(hy));
    h = ((uint32_t)hy << 16) | hx;
    unsigned short lx = __bfloat16_as_ushort(__float2bfloat16(x - fx));
    unsigned short ly = __bfloat16_as_ushort(__float2bfloat16(y - fy));
    l = ((uint32_t)ly << 16) | lx;
}

// smem layout (dynamic): Q/K/V split tiles, 128 rows x 64 bf16 (128 B/row)
static constexpr int OF_QH  = 0;
static constexpr int OF_QL  = 16384;
static constexpr int OF_KH  = 32768;
static constexpr int OF_KL  = 49152;
static constexpr int OF_VH  = 65536;
static constexpr int OF_VL  = 81920;
static constexpr int OF_MSK = 98304;          // 128 f32
static constexpr int OF_K0  = OF_MSK + 512;   // 64 f32
static constexpr int OF_V0  = OF_K0 + 256;    // 64 f32
static constexpr int OF_EG  = OF_V0 + 256;    // 128 f32
static constexpr int SMEM_BYTES = OF_EG + 512;  // ~97.5 KB

// ==================== main block-local attention kernel ====================
__global__ __launch_bounds__(256, 2)
void attn_block_kernel(const float* __restrict__ Q, const float* __restrict__ K,
                       const float* __restrict__ V, const float* __restrict__ M,
                       float* __restrict__ O) {
    extern __shared__ __align__(128) char smem[];
    const uint32_t sb = smem_u32(smem);
    const int tid  = threadIdx.x;
    const int lane = tid & 31;
    const int warp = tid >> 5;
    const int b    = blockIdx.x;
    const int bh   = blockIdx.y;
    const int nIdx = bh / NH;

    const float* Qg = Q + ((size_t)bh * TSEQ + (size_t)b * BS) * DH;
    const float* Kg = K + (size_t)bh * TSEQ * DH;
    const float* Vg = V + (size_t)bh * TSEQ * DH;
    const float* Mr = M + (size_t)nIdx * TSEQ;
    float*       Og = O + ((size_t)bh * TSEQ + (size_t)b * BS) * DH;

    float* msk = (float*)(smem + OF_MSK);
    float* k0s = (float*)(smem + OF_K0);
    float* v0s = (float*)(smem + OF_V0);
    float* egs = (float*)(smem + OF_EG);

    if (tid < DH) { k0s[tid] = Kg[tid]; v0s[tid] = Vg[tid]; }

    // ---- Q tile -> smem (split hi/lo, SW128) ----
    {
        const float4* qp = (const float4*)Qg;
        for (int f = tid; f < 2048; f += 256) {
            const uint32_t sw = SW128((uint32_t)(f * 8));
            uint32_t h0, l0, h1, l1;
            float4 qv = qp[f];
            pksp(qv.x, qv.y, h0, l0); pksp(qv.z, qv.w, h1, l1);
            *(uint2*)(smem + OF_QH + sw) = make_uint2(h0, h1);
            *(uint2*)(smem + OF_QL + sw) = make_uint2(l0, l1);
        }
    }
    __syncthreads();

    // ---- global-token seed e_g[r] = exp(0.125 * q_r . k0) ----
    const int r0 = warp * 16;
    {
        const int rr = r0 + (lane >> 1);
        const int hf = lane & 1;
        const float* qr = Qg + (size_t)rr * DH + hf * 32;
        float p = 0.f;
        #pragma unroll
        for (int i = 0; i < 32; i++) p += qr[i] * k0s[hf * 32 + i];
        p += __shfl_xor_sync(0xffffffffu, p, 1);
        if (hf == 0) egs[rr] = __expf(p * 0.125f);
    }
    __syncwarp();

    // ---- A fragments: qh resident (16 regs); ql streamed later ----
    const uint32_t a_addr0 = (uint32_t)((r0 + (lane & 15)) * 128 + ((lane >> 4) & 1) * 16);
    uint32_t qh[4][4];
    #pragma unroll
    for (int ks = 0; ks < 4; ks++)
        ldsm_x4(qh[ks], sb + OF_QH + SW128(a_addr0 + ks * 32));

    float o[8][4];
    #pragma unroll
    for (int i = 0; i < 8; i++)
        #pragma unroll
        for (int j = 0; j < 4; j++) o[i][j] = 0.f;
    float lr0 = 0.f, lr8 = 0.f;

    // B-frag lane address components
    const int k_rowoff = ((lane >> 4) << 3) + (lane & 7);
    const int k_coloff = ((lane >> 3) & 1) * 16;
    const int v_rowoff = (lane & 15);
    const int v_coloff = (lane >> 4) * 16;

    for (int kb = b - 1; kb <= b + 1; kb++) {
        if (kb < 0 || kb >= NB) continue;
        const int kb0 = kb * BS;

        __syncthreads();   // previous tile fully consumed
        {
            const float4* kp = (const float4*)(Kg + (size_t)kb0 * DH);
            const float4* vp = (const float4*)(Vg + (size_t)kb0 * DH);
            for (int f = tid; f < 2048; f += 256) {
                const uint32_t sw = SW128((uint32_t)(f * 8));
                uint32_t h0, l0, h1, l1;
                float4 kv = kp[f];
                pksp(kv.x, kv.y, h0, l0); pksp(kv.z, kv.w, h1, l1);
                *(uint2*)(smem + OF_KH + sw) = make_uint2(h0, h1);
                *(uint2*)(smem + OF_KL + sw) = make_uint2(l0, l1);
                float4 vv = vp[f];
                pksp(vv.x, vv.y, h0, l0); pksp(vv.z, vv.w, h1, l1);
                *(uint2*)(smem + OF_VH + sw) = make_uint2(h0, h1);
                *(uint2*)(smem + OF_VL + sw) = make_uint2(l0, l1);
            }
            if (tid < BS) msk[tid] = Mr[kb0 + tid];
        }
        __syncthreads();

        #pragma unroll
        for (int h = 0; h < 2; h++) {        // 64-key halves
            #pragma unroll
            for (int c = 0; c < 2; c++) {    // 32-key chunks
                const int key0 = h * 64 + c * 32;

                // ---- S chunk = Q K^T (3-term split, term-major, dist-4) ----
                float s[4][4];
                #pragma unroll
                for (int i = 0; i < 4; i++)
                    #pragma unroll
                    for (int j = 0; j < 4; j++) s[i][j] = 0.f;

                #pragma unroll
                for (int ks = 0; ks < 4; ks++) {
                    uint32_t ql4[4];
                    ldsm_x4(ql4, sb + OF_QL + SW128(a_addr0 + ks * 32));
                    uint32_t BH[4][2], BL[4][2];
                    #pragma unroll
                    for (int np = 0; np < 2; np++) {
                        const int keyrow = key0 + np * 16 + k_rowoff;
                        const uint32_t off = (uint32_t)(keyrow * 128 + ks * 32 + k_coloff);
                        const uint32_t swo = SW128(off);
                        uint32_t r[4];
                        ldsm_x4(r, sb + OF_KH + swo);
                        BH[2*np][0] = r[0]; BH[2*np][1] = r[1];
                        BH[2*np+1][0] = r[2]; BH[2*np+1][1] = r[3];
                        ldsm_x4(r, sb + OF_KL + swo);
                        BL[2*np][0] = r[0]; BL[2*np][1] = r[1];
                        BL[2*np+1][0] = r[2]; BL[2*np+1][1] = r[3];
                    }
                    #pragma unroll
                    for (int nt = 0; nt < 4; nt++) mma_bf16(s[nt], qh[ks], BH[nt]);
                    #pragma unroll
                    for (int nt = 0; nt < 4; nt++) mma_bf16(s[nt], qh[ks], BL[nt]);
                    #pragma unroll
                    for (int nt = 0; nt < 4; nt++) mma_bf16(s[nt], ql4,   BH[nt]);
                }

                // ---- softmax (no-max) + PV for the chunk's two kt groups ----
                #pragma unroll
                for (int u = 0; u < 2; u++) {
                    const int kt = 2 * c + u;      // 16-key group within half
                    float e[2][4];
                    #pragma unroll
                    for (int v = 0; v < 2; v++) {
                        const int ntl = 2 * u + v;
                        #pragma unroll
                        for (int j = 0; j < 4; j++) {
                            const int col = key0 + ntl * 8 + (lane & 3) * 2 + (j & 1);
                            float ev = __expf(fmaf(s[ntl][j], 0.125f, msk[col]));
                            if (kb0 + col == 0) ev = 0.f;   // window never sees pos 0
                            e[v][j] = ev;
                            if (j < 2) lr0 += ev; else lr8 += ev;
                        }
                    }
                    uint32_t ph[4], pl[4];
                    pksp(e[0][0], e[0][1], ph[0], pl[0]);
                    pksp(e[0][2], e[0][3], ph[1], pl[1]);
                    pksp(e[1][0], e[1][1], ph[2], pl[2]);
                    pksp(e[1][2], e[1][3], ph[3], pl[3]);

                    const int vrow = h * 64 + kt * 16 + v_rowoff;
                    #pragma unroll
                    for (int g = 0; g < 2; g++) {       // dim groups of 32
                        uint32_t VH[4][2], VL[4][2];
                        #pragma unroll
                        for (int np = 0; np < 2; np++) {
                            const uint32_t off =
                                (uint32_t)(vrow * 128 + (g * 2 + np) * 32 + v_coloff);
                            const uint32_t swo = SW128(off);
                            uint32_t r[4];
                            ldsm_x4_t(r, sb + OF_VH + swo);
                            VH[2*np][0] = r[0]; VH[2*np][1] = r[1];
                            VH[2*np+1][0] = r[2]; VH[2*np+1][1] = r[3];
                            ldsm_x4_t(r, sb + OF_VL + swo);
                            VL[2*np][0] = r[0]; VL[2*np][1] = r[1];
                            VL[2*np+1][0] = r[2]; VL[2*np+1][1] = r[3];
                        }
                        #pragma unroll
                        for (int n2 = 0; n2 < 4; n2++) mma_bf16(o[g*4+n2], ph, VH[n2]);
                        #pragma unroll
                        for (int n2 = 0; n2 < 4; n2++) mma_bf16(o[g*4+n2], ph, VL[n2]);
                        #pragma unroll
                        for (int n2 = 0; n2 < 4; n2++) mma_bf16(o[g*4+n2], pl, VH[n2]);
                    }
                }
            }
        }
    }

    // ---- epilogue: add global token, normalize, store ----
    lr0 += __shfl_xor_sync(0xffffffffu, lr0, 1);
    lr0 += __shfl_xor_sync(0xffffffffu, lr0, 2);
    lr8 += __shfl_xor_sync(0xffffffffu, lr8, 1);
    lr8 += __shfl_xor_sync(0xffffffffu, lr8, 2);
    const int r = lane >> 2;
    const float eg0 = egs[r0 + r];
    const float eg8 = egs[r0 + r + 8];
    const float il0 = 1.f / (lr0 + eg0);
    const float il8 = 1.f / (lr8 + eg8);
    #pragma unroll
    for (int n2 = 0; n2 < 8; n2++) {
        const int d = n2 * 8 + (lane & 3) * 2;
        float2 w0 = make_float2((o[n2][0] + eg0 * v0s[d])     * il0,
                                (o[n2][1] + eg0 * v0s[d + 1]) * il0);
        float2 w8 = make_float2((o[n2][2] + eg8 * v0s[d])     * il8,
                                (o[n2][3] + eg8 * v0s[d + 1]) * il8);
        *(float2*)(Og + (size_t)(r0 + r)     * DH + d) = w0;
        *(float2*)(Og + (size_t)(r0 + r + 8) * DH + d) = w8;
    }
}

// ============== row-0 full attention (split-K partials + reduce) ==========
__device__ float g_part[NBH][8][DH];
__device__ float g_plsum[NBH][8];

__global__ __launch_bounds__(256)
void row0_partial_kernel(const float* __restrict__ Q, const float* __restrict__ K,
                         const float* __restrict__ V, const float* __restrict__ M) {
    const int st = blockIdx.x;     // stripe of 512 keys
    const int bh = blockIdx.y;
    const int nIdx = bh / NH;
    const int tid = threadIdx.x;
    const int j0 = st * 512;

    __shared__ float q0[DH];
    __shared__ float esm[512];
    __shared__ float red[256];
    __shared__ float part[4][DH];

    const float* Qg = Q + (size_t)bh * TSEQ * DH;
    const float* Kg = K + (size_t)bh * TSEQ * DH;
    const float* Vg = V + (size_t)bh * TSEQ * DH;
    const float* Mr = M + (size_t)nIdx * TSEQ;

    if (tid < DH) q0[tid] = Qg[tid];
    __syncthreads();

    float l = 0.f;
    for (int j = tid; j < 512; j += 256) {
        const int pos = j0 + j;
        float dot = 0.f;
        const float4* kp = (const float4*)(Kg + (size_t)pos * DH);
        #pragma unroll
        for (int i = 0; i < 16; i++) {
            float4 kv = kp[i];
            dot += q0[4*i]*kv.x + q0[4*i+1]*kv.y + q0[4*i+2]*kv.z + q0[4*i+3]*kv.w;
        }
        float e = __expf(fmaf(dot, 0.125f, Mr[pos]));
        esm[j] = e;
        l += e;
    }
    red[tid] = l; __syncthreads();
    for (int s = 128; s > 0; s >>= 1) {
        if (tid < s) red[tid] += red[tid + s];
        __syncthreads();
    }
    if (tid == 0) g_plsum[bh][st] = red[0];

    const int dm = tid & 63, q = tid >> 6;
    float a = 0.f;
    for (int k = q * 128; k < q * 128 + 128; k++)
        a += esm[k] * Vg[(size_t)(j0 + k) * DH + dm];
    part[q][dm] = a;
    __syncthreads();
    if (tid < DH)
        g_part[bh][st][tid] = part[0][tid] + part[1][tid] + part[2][tid] + part[3][tid];
}

__global__ void row0_reduce_kernel(float* __restrict__ O) {
    const int bh = blockIdx.x;
    const int d = threadIdx.x;
    float s = 0.f, l = 0.f;
    #pragma unroll
    for (int st = 0; st < 8; st++) { s += g_part[bh][st][d]; l += g_plsum[bh][st]; }
    O[(size_t)bh * TSEQ * DH + d] = s / l;
}

// ================================ launch ===================================
extern "C" void kernel_launch(void* const* d_in, const int* in_sizes, int n_in,
                              void* d_out, int out_size) {
    const float* Q = (const float*)d_in[0];
    const float* K = (const float*)d_in[1];
    const float* V = (const float*)d_in[2];
    const float* M = (const float*)d_in[3];
    float* O = (float*)d_out;

    cudaFuncSetAttribute(attn_block_kernel,
                         cudaFuncAttributeMaxDynamicSharedMemorySize, SMEM_BYTES);
    dim3 grid(NB, NBH);
    attn_block_kernel<<<grid, 256, SMEM_BYTES>>>(Q, K, V, M, O);
    dim3 gridp(8, NBH);
    row0_partial_kernel<<<gridp, 256>>>(Q, K, V, M);
    row0_reduce_kernel<<<NBH, DH>>>(O);
}

// round 8
// speedup vs baseline: 1.0915x; 1.0915x over previous
#include <cuda_runtime.h>
#include <cuda_bf16.h>
#include <cstdint>

#define TSEQ 4096
#define DH   64
#define BS   128
#define NB   32
#define NH   16
#define NBH  32

// ---------------- low-level helpers (sm_100 base ISA only) ----------------
__device__ __forceinline__ uint32_t smem_u32(const void* p) {
    uint32_t a;
    asm("{ .reg .u64 t; cvta.to.shared.u64 t, %1; cvt.u32.u64 %0, t; }"
        : "=r"(a) : "l"(p));
    return a;
}
__device__ __forceinline__ void mma_bf16(float* d, const uint32_t* a, const uint32_t* b) {
    asm volatile(
        "mma.sync.aligned.m16n8k16.row.col.f32.bf16.bf16.f32 "
        "{%0,%1,%2,%3}, {%4,%5,%6,%7}, {%8,%9}, {%0,%1,%2,%3};"
        : "+f"(d[0]), "+f"(d[1]), "+f"(d[2]), "+f"(d[3])
        : "r"(a[0]), "r"(a[1]), "r"(a[2]), "r"(a[3]), "r"(b[0]), "r"(b[1]));
}
__device__ __forceinline__ void ldsm_x4(uint32_t* r, uint32_t addr) {
    asm volatile("ldmatrix.sync.aligned.m8n8.x4.shared.b16 {%0,%1,%2,%3}, [%4];"
                 : "=r"(r[0]), "=r"(r[1]), "=r"(r[2]), "=r"(r[3]) : "r"(addr));
}
__device__ __forceinline__ void ldsm_x4_t(uint32_t* r, uint32_t addr) {
    asm volatile("ldmatrix.sync.aligned.m8n8.x4.trans.shared.b16 {%0,%1,%2,%3}, [%4];"
                 : "=r"(r[0]), "=r"(r[1]), "=r"(r[2]), "=r"(r[3]) : "r"(addr));
}
#define SW128(x) ((x) ^ (((x) >> 3) & 0x70))

// split fp32 pair -> (hi bf16x2, lo bf16x2)
__device__ __forceinline__ void pksp(float x, float y, uint32_t& h, uint32_t& l) {
    unsigned short hx = __bfloat16_as_ushort(__float2bfloat16(x));
    unsigned short hy = __bfloat16_as_ushort(__float2bfloat16(y));
    float fx = __bfloat162float(__ushort_as_bfloat16(hx));
    float fy = __bfloat162float(__ushort_as_bfloat16(hy));
    h = ((uint32_t)hy << 16) | hx;
    unsigned short lx = __bfloat16_as_ushort(__float2bfloat16(x - fx));
    unsigned short ly = __bfloat16_as_ushort(__float2bfloat16(y - fy));
    l = ((uint32_t)ly << 16) | lx;
}

// smem layout: two K/V slots (double buffered), each 64 KB:
//   slot s at s*65536: KH +0, KL +16384, VH +32768, VL +49152
static constexpr int SLOT_STRIDE = 65536;
static constexpr int OF_MSK = 131072;            // 2 x 128 f32 (per slot)
static constexpr int OF_K0  = OF_MSK + 1024;     // 64 f32
static constexpr int OF_V0  = OF_K0 + 256;       // 64 f32
static constexpr int OF_EG  = OF_V0 + 256;       // 128 f32
static constexpr int SMEM_BYTES = OF_EG + 512;   // ~130.5 KB -> 1 CTA/SM

// ==================== main block-local attention kernel ====================
__global__ __launch_bounds__(256, 1)
void attn_block_kernel(const float* __restrict__ Q, const float* __restrict__ K,
                       const float* __restrict__ V, const float* __restrict__ M,
                       float* __restrict__ O) {
    extern __shared__ __align__(128) char smem[];
    const uint32_t sb = smem_u32(smem);
    const int tid  = threadIdx.x;
    const int lane = tid & 31;
    const int warp = tid >> 5;
    const int b    = blockIdx.x;
    const int bh   = blockIdx.y;
    const int nIdx = bh / NH;

    const float* Qg = Q + ((size_t)bh * TSEQ + (size_t)b * BS) * DH;
    const float* Kg = K + (size_t)bh * TSEQ * DH;
    const float* Vg = V + (size_t)bh * TSEQ * DH;
    const float* Mr = M + (size_t)nIdx * TSEQ;
    float*       Og = O + ((size_t)bh * TSEQ + (size_t)b * BS) * DH;

    float* k0s = (float*)(smem + OF_K0);
    float* v0s = (float*)(smem + OF_V0);
    float* egs = (float*)(smem + OF_EG);

    if (tid < DH) { k0s[tid] = Kg[tid]; v0s[tid] = Vg[tid]; }

    // ---- Q fragments (hi/lo) register-resident across all key blocks ----
    const int r0 = warp * 16;
    uint32_t qh[4][4], ql[4][4];
    #pragma unroll
    for (int ks = 0; ks < 4; ks++)
        #pragma unroll
        for (int i = 0; i < 4; i++) {
            const int rr = r0 + (lane >> 2) + (i & 1) * 8;
            const int cc = ks * 16 + (lane & 3) * 2 + (i >> 1) * 8;
            float2 v = *(const float2*)(Qg + rr * DH + cc);
            pksp(v.x, v.y, qh[ks][i], ql[ks][i]);
        }
    __syncthreads();

    // ---- global-token seed e_g[r] = exp(0.125 * q_r . k0) ----
    {
        const int rr = r0 + (lane >> 1);
        const int hf = lane & 1;
        const float* qr = Qg + (size_t)rr * DH + hf * 32;
        float p = 0.f;
        #pragma unroll
        for (int i = 0; i < 32; i++) p += qr[i] * k0s[hf * 32 + i];
        p += __shfl_xor_sync(0xffffffffu, p, 1);
        if (hf == 0) egs[rr] = __expf(p * 0.125f);
    }
    __syncwarp();

    float o[8][4];
    #pragma unroll
    for (int i = 0; i < 8; i++)
        #pragma unroll
        for (int j = 0; j < 4; j++) o[i][j] = 0.f;
    float lr0 = 0.f, lr8 = 0.f;

    const int k_rowoff = ((lane >> 4) << 3) + (lane & 7);
    const int k_coloff = ((lane >> 3) & 1) * 16;
    const int v_rowoff = (lane & 15);
    const int v_coloff = (lane >> 4) * 16;

    // valid key blocks
    int kbs[3]; int nv = 0;
    for (int kb = b - 1; kb <= b + 1; kb++)
        if (kb >= 0 && kb < NB) kbs[nv++] = kb;

    // ---- preload: convert block 0 into slot 0 ----
    {
        const int kb0 = kbs[0] * BS;
        const float4* kp = (const float4*)(Kg + (size_t)kb0 * DH);
        const float4* vp = (const float4*)(Vg + (size_t)kb0 * DH);
        #pragma unroll
        for (int f = 0; f < 8; f++) {
            const int idx = tid + f * 256;
            const uint32_t sw = SW128((uint32_t)(idx * 8));
            uint32_t h0, l0, h1, l1;
            float4 kv = kp[idx];
            pksp(kv.x, kv.y, h0, l0); pksp(kv.z, kv.w, h1, l1);
            *(uint2*)(smem + 0     + sw) = make_uint2(h0, h1);
            *(uint2*)(smem + 16384 + sw) = make_uint2(l0, l1);
            float4 vv = vp[idx];
            pksp(vv.x, vv.y, h0, l0); pksp(vv.z, vv.w, h1, l1);
            *(uint2*)(smem + 32768 + sw) = make_uint2(h0, h1);
            *(uint2*)(smem + 49152 + sw) = make_uint2(l0, l1);
        }
        if (tid < BS) ((float*)(smem + OF_MSK))[tid] = Mr[kb0 + tid];
    }

    for (int i = 0; i < nv; i++) {
        __syncthreads();   // converts for slot i%2 complete; slot (i+1)%2 free
        const int kb0  = kbs[i] * BS;
        const int slot = (i & 1) * SLOT_STRIDE;
        float* msk = (float*)(smem + OF_MSK + (i & 1) * 512);
        const bool more = (i + 1 < nv);
        const int nkb0  = more ? kbs[i + 1] * BS : 0;
        const int nslot = ((i + 1) & 1) * SLOT_STRIDE;

        #pragma unroll
        for (int h = 0; h < 2; h++) {      // two 64-key halves
            // ---- S = Q K^T (3-term split, term-major dist-8) ----
            float s[8][4];
            #pragma unroll
            for (int ii = 0; ii < 8; ii++)
                #pragma unroll
                for (int j = 0; j < 4; j++) s[ii][j] = 0.f;

            #pragma unroll
            for (int ks = 0; ks < 4; ks++) {
                uint32_t BH[8][2], BL[8][2];
                #pragma unroll
                for (int np = 0; np < 4; np++) {
                    const int keyrow = h * 64 + np * 16 + k_rowoff;
                    const uint32_t swo = SW128((uint32_t)(keyrow * 128 + ks * 32 + k_coloff));
                    uint32_t r[4];
                    ldsm_x4(r, sb + slot + 0 + swo);
                    BH[2*np][0] = r[0]; BH[2*np][1] = r[1];
                    BH[2*np+1][0] = r[2]; BH[2*np+1][1] = r[3];
                    ldsm_x4(r, sb + slot + 16384 + swo);
                    BL[2*np][0] = r[0]; BL[2*np][1] = r[1];
                    BL[2*np+1][0] = r[2]; BL[2*np+1][1] = r[3];
                }
                #pragma unroll
                for (int nt = 0; nt < 8; nt++) mma_bf16(s[nt], qh[ks], BH[nt]);
                #pragma unroll
                for (int nt = 0; nt < 8; nt++) mma_bf16(s[nt], qh[ks], BL[nt]);
                #pragma unroll
                for (int nt = 0; nt < 8; nt++) mma_bf16(s[nt], ql[ks], BH[nt]);
            }

            // ---- pipelined convert of NEXT block (K after h0, V+msk after h1) ----
            if (more) {
                if (h == 0) {
                    const float4* kp = (const float4*)(Kg + (size_t)nkb0 * DH);
                    #pragma unroll
                    for (int f = 0; f < 8; f++) {
                        const int idx = tid + f * 256;
                        const uint32_t sw = SW128((uint32_t)(idx * 8));
                        uint32_t h0, l0, h1, l1;
                        float4 kv = kp[idx];
                        pksp(kv.x, kv.y, h0, l0); pksp(kv.z, kv.w, h1, l1);
                        *(uint2*)(smem + nslot + 0     + sw) = make_uint2(h0, h1);
                        *(uint2*)(smem + nslot + 16384 + sw) = make_uint2(l0, l1);
                    }
                } else {
                    const float4* vp = (const float4*)(Vg + (size_t)nkb0 * DH);
                    #pragma unroll
                    for (int f = 0; f < 8; f++) {
                        const int idx = tid + f * 256;
                        const uint32_t sw = SW128((uint32_t)(idx * 8));
                        uint32_t h0, l0, h1, l1;
                        float4 vv = vp[idx];
                        pksp(vv.x, vv.y, h0, l0); pksp(vv.z, vv.w, h1, l1);
                        *(uint2*)(smem + nslot + 32768 + sw) = make_uint2(h0, h1);
                        *(uint2*)(smem + nslot + 49152 + sw) = make_uint2(l0, l1);
                    }
                    if (tid < BS)
                        ((float*)(smem + OF_MSK + ((i + 1) & 1) * 512))[tid] = Mr[nkb0 + tid];
                }
            }

            // ---- softmax (no-max) -> P fragments -> PV (term-major) ----
            #pragma unroll
            for (int kt = 0; kt < 4; kt++) {
                uint32_t VH[8][2], VL[8][2];
                #pragma unroll
                for (int np = 0; np < 4; np++) {
                    const int vrow = h * 64 + kt * 16 + v_rowoff;
                    const uint32_t swo = SW128((uint32_t)(vrow * 128 + np * 32 + v_coloff));
                    uint32_t r[4];
                    ldsm_x4_t(r, sb + slot + 32768 + swo);
                    VH[2*np][0] = r[0]; VH[2*np][1] = r[1];
                    VH[2*np+1][0] = r[2]; VH[2*np+1][1] = r[3];
                    ldsm_x4_t(r, sb + slot + 49152 + swo);
                    VL[2*np][0] = r[0]; VL[2*np][1] = r[1];
                    VL[2*np+1][0] = r[2]; VL[2*np+1][1] = r[3];
                }

                float e[2][4];
                #pragma unroll
                for (int u = 0; u < 2; u++) {
                    const int nt = 2 * kt + u;
                    #pragma unroll
                    for (int j = 0; j < 4; j++) {
                        const int col = h * 64 + nt * 8 + (lane & 3) * 2 + (j & 1);
                        float ev = __expf(fmaf(s[nt][j], 0.125f, msk[col]));
                        if (kb0 + col == 0) ev = 0.f;   // window never sees pos 0
                        e[u][j] = ev;
                        if (j < 2) lr0 += ev; else lr8 += ev;
                    }
                }
                uint32_t ph[4], pl[4];
                pksp(e[0][0], e[0][1], ph[0], pl[0]);
                pksp(e[0][2], e[0][3], ph[1], pl[1]);
                pksp(e[1][0], e[1][1], ph[2], pl[2]);
                pksp(e[1][2], e[1][3], ph[3], pl[3]);

                #pragma unroll
                for (int n2 = 0; n2 < 8; n2++) mma_bf16(o[n2], ph, VH[n2]);
                #pragma unroll
                for (int n2 = 0; n2 < 8; n2++) mma_bf16(o[n2], ph, VL[n2]);
                #pragma unroll
                for (int n2 = 0; n2 < 8; n2++) mma_bf16(o[n2], pl, VH[n2]);
            }
        }
    }

    // ---- epilogue: add global token, normalize, store ----
    lr0 += __shfl_xor_sync(0xffffffffu, lr0, 1);
    lr0 += __shfl_xor_sync(0xffffffffu, lr0, 2);
    lr8 += __shfl_xor_sync(0xffffffffu, lr8, 1);
    lr8 += __shfl_xor_sync(0xffffffffu, lr8, 2);
    const int r = lane >> 2;
    const float eg0 = egs[r0 + r];
    const float eg8 = egs[r0 + r + 8];
    const float il0 = 1.f / (lr0 + eg0);
    const float il8 = 1.f / (lr8 + eg8);
    #pragma unroll
    for (int n2 = 0; n2 < 8; n2++) {
        const int d = n2 * 8 + (lane & 3) * 2;
        float2 w0 = make_float2((o[n2][0] + eg0 * v0s[d])     * il0,
                                (o[n2][1] + eg0 * v0s[d + 1]) * il0);
        float2 w8 = make_float2((o[n2][2] + eg8 * v0s[d])     * il8,
                                (o[n2][3] + eg8 * v0s[d + 1]) * il8);
        *(float2*)(Og + (size_t)(r0 + r)     * DH + d) = w0;
        *(float2*)(Og + (size_t)(r0 + r + 8) * DH + d) = w8;
    }
}

// ============== row-0 full attention (split-K partials + reduce) ==========
__device__ float g_part[NBH][8][DH];
__device__ float g_plsum[NBH][8];

__global__ __launch_bounds__(256)
void row0_partial_kernel(const float* __restrict__ Q, const float* __restrict__ K,
                         const float* __restrict__ V, const float* __restrict__ M) {
    const int st = blockIdx.x;     // stripe of 512 keys
    const int bh = blockIdx.y;
    const int nIdx = bh / NH;
    const int tid = threadIdx.x;
    const int j0 = st * 512;

    __shared__ float q0[DH];
    __shared__ float esm[512];
    __shared__ float red[256];
    __shared__ float part[4][DH];

    const float* Qg = Q + (size_t)bh * TSEQ * DH;
    const float* Kg = K + (size_t)bh * TSEQ * DH;
    const float* Vg = V + (size_t)bh * TSEQ * DH;
    const float* Mr = M + (size_t)nIdx * TSEQ;

    if (tid < DH) q0[tid] = Qg[tid];
    __syncthreads();

    float l = 0.f;
    for (int j = tid; j < 512; j += 256) {
        const int pos = j0 + j;
        float dot = 0.f;
        const float4* kp = (const float4*)(Kg + (size_t)pos * DH);
        #pragma unroll
        for (int i = 0; i < 16; i++) {
            float4 kv = kp[i];
            dot += q0[4*i]*kv.x + q0[4*i+1]*kv.y + q0[4*i+2]*kv.z + q0[4*i+3]*kv.w;
        }
        float e = __expf(fmaf(dot, 0.125f, Mr[pos]));
        esm[j] = e;
        l += e;
    }
    red[tid] = l; __syncthreads();
    for (int s = 128; s > 0; s >>= 1) {
        if (tid < s) red[tid] += red[tid + s];
        __syncthreads();
    }
    if (tid == 0) g_plsum[bh][st] = red[0];

    const int dm = tid & 63, q = tid >> 6;
    float a = 0.f;
    for (int k = q * 128; k < q * 128 + 128; k++)
        a += esm[k] * Vg[(size_t)(j0 + k) * DH + dm];
    part[q][dm] = a;
    __syncthreads();
    if (tid < DH)
        g_part[bh][st][tid] = part[0][tid] + part[1][tid] + part[2][tid] + part[3][tid];
}

__global__ void row0_reduce_kernel(float* __restrict__ O) {
    const int bh = blockIdx.x;
    const int d = threadIdx.x;
    float s = 0.f, l = 0.f;
    #pragma unroll
    for (int st = 0; st < 8; st++) { s += g_part[bh][st][d]; l += g_plsum[bh][st]; }
    O[(size_t)bh * TSEQ * DH + d] = s / l;
}

// ================================ launch ===================================
extern "C" void kernel_launch(void* const* d_in, const int* in_sizes, int n_in,
                              void* d_out, int out_size) {
    const float* Q = (const float*)d_in[0];
    const float* K = (const float*)d_in[1];
    const float* V = (const float*)d_in[2];
    const float* M = (const float*)d_in[3];
    float* O = (float*)d_out;

    cudaFuncSetAttribute(attn_block_kernel,
                         cudaFuncAttributeMaxDynamicSharedMemorySize, SMEM_BYTES);
    dim3 grid(NB, NBH);
    attn_block_kernel<<<grid, 256, SMEM_BYTES>>>(Q, K, V, M, O);
    dim3 gridp(8, NBH);
    row0_partial_kernel<<<gridp, 256>>>(Q, K, V, M);
    row0_reduce_kernel<<<NBH, DH>>>(O);
}

// round 10
// speedup vs baseline: 1.3333x; 1.2215x over previous
#include <cuda_runtime.h>
#include <cuda_fp16.h>
#include <cstdint>

#define TSEQ 4096
#define DH   64
#define BS   128
#define NB   32
#define NH   16
#define NBH  32

// ---------------- low-level helpers (sm_100 base ISA only) ----------------
__device__ __forceinline__ uint32_t smem_u32(const void* p) {
    uint32_t a;
    asm("{ .reg .u64 t; cvta.to.shared.u64 t, %1; cvt.u32.u64 %0, t; }"
        : "=r"(a) : "l"(p));
    return a;
}
__device__ __forceinline__ void mma_f16(float* d, const uint32_t* a, const uint32_t* b) {
    asm volatile(
        "mma.sync.aligned.m16n8k16.row.col.f32.f16.f16.f32 "
        "{%0,%1,%2,%3}, {%4,%5,%6,%7}, {%8,%9}, {%0,%1,%2,%3};"
        : "+f"(d[0]), "+f"(d[1]), "+f"(d[2]), "+f"(d[3])
        : "r"(a[0]), "r"(a[1]), "r"(a[2]), "r"(a[3]), "r"(b[0]), "r"(b[1]));
}
__device__ __forceinline__ void ldsm_x4(uint32_t* r, uint32_t addr) {
    asm volatile("ldmatrix.sync.aligned.m8n8.x4.shared.b16 {%0,%1,%2,%3}, [%4];"
                 : "=r"(r[0]), "=r"(r[1]), "=r"(r[2]), "=r"(r[3]) : "r"(addr));
}
__device__ __forceinline__ void ldsm_x4_t(uint32_t* r, uint32_t addr) {
    asm volatile("ldmatrix.sync.aligned.m8n8.x4.trans.shared.b16 {%0,%1,%2,%3}, [%4];"
                 : "=r"(r[0]), "=r"(r[1]), "=r"(r[2]), "=r"(r[3]) : "r"(addr));
}
#define SW128(x) ((x) ^ (((x) >> 3) & 0x70))

// pack two floats to fp16x2 (single rounding)
__device__ __forceinline__ uint32_t pkh(float x, float y) {
    return ((uint32_t)__half_as_ushort(__float2half_rn(y)) << 16)
         |  (uint32_t)__half_as_ushort(__float2half_rn(x));
}
// exact-ish split: fp16 hi + fp16 lo (22-bit effective)
__device__ __forceinline__ void pksp16(float x, float y, uint32_t& h, uint32_t& l) {
    __half hx = __float2half_rn(x), hy = __float2half_rn(y);
    h = ((uint32_t)__half_as_ushort(hy) << 16) | __half_as_ushort(hx);
    __half lx = __float2half_rn(x - __half2float(hx));
    __half ly = __float2half_rn(y - __half2float(hy));
    l = ((uint32_t)__half_as_ushort(ly) << 16) | __half_as_ushort(lx);
}

// smem: 2 slots, each: Kh fp16 128x64 @+0 (16KB), Vh @+16384
static constexpr int SLOT_STRIDE = 32768;
static constexpr int OF_MSK = 65536;             // 2 x 128 f32
static constexpr int OF_K0  = OF_MSK + 1024;     // 64 f32
static constexpr int OF_V0  = OF_K0 + 256;       // 64 f32
static constexpr int OF_EG  = OF_V0 + 256;       // 128 f32
static constexpr int SMEM_BYTES = OF_EG + 512;   // ~66 KB -> 2 CTAs/SM

// ==================== main block-local attention kernel ====================
__global__ __launch_bounds__(256, 2)
void attn_block_kernel(const float* __restrict__ Q, const float* __restrict__ K,
                       const float* __restrict__ V, const float* __restrict__ M,
                       float* __restrict__ O) {
    extern __shared__ __align__(128) char smem[];
    const uint32_t sb = smem_u32(smem);
    const int tid  = threadIdx.x;
    const int lane = tid & 31;
    const int warp = tid >> 5;
    const int b    = blockIdx.x;
    const int bh   = blockIdx.y;
    const int nIdx = bh / NH;

    const float* Qg = Q + ((size_t)bh * TSEQ + (size_t)b * BS) * DH;
    const float* Kg = K + (size_t)bh * TSEQ * DH;
    const float* Vg = V + (size_t)bh * TSEQ * DH;
    const float* Mr = M + (size_t)nIdx * TSEQ;
    float*       Og = O + ((size_t)bh * TSEQ + (size_t)b * BS) * DH;

    float* k0s = (float*)(smem + OF_K0);
    float* v0s = (float*)(smem + OF_V0);
    float* egs = (float*)(smem + OF_EG);

    if (tid < DH) { k0s[tid] = Kg[tid]; v0s[tid] = Vg[tid]; }

    // ---- Q fragments fp16 hi/lo, register-resident ----
    const int r0 = warp * 16;
    uint32_t qh[4][4], ql[4][4];
    #pragma unroll
    for (int ks = 0; ks < 4; ks++)
        #pragma unroll
        for (int i = 0; i < 4; i++) {
            const int rr = r0 + (lane >> 2) + (i & 1) * 8;
            const int cc = ks * 16 + (lane & 3) * 2 + (i >> 1) * 8;
            float2 v = *(const float2*)(Qg + rr * DH + cc);
            pksp16(v.x, v.y, qh[ks][i], ql[ks][i]);
        }
    __syncthreads();

    // ---- global-token seed e_g[r] = exp(0.125 * q_r . k0) ----
    {
        const int rr = r0 + (lane >> 1);
        const int hf = lane & 1;
        const float* qr = Qg + (size_t)rr * DH + hf * 32;
        float p = 0.f;
        #pragma unroll
        for (int i = 0; i < 32; i++) p += qr[i] * k0s[hf * 32 + i];
        p += __shfl_xor_sync(0xffffffffu, p, 1);
        if (hf == 0) egs[rr] = __expf(p * 0.125f);
    }
    __syncwarp();

    float o[8][4];
    #pragma unroll
    for (int i = 0; i < 8; i++)
        #pragma unroll
        for (int j = 0; j < 4; j++) o[i][j] = 0.f;
    float lr0 = 0.f, lr8 = 0.f;

    const int k_rowoff = ((lane >> 4) << 3) + (lane & 7);
    const int k_coloff = ((lane >> 3) & 1) * 16;
    const int v_rowoff = (lane & 15);
    const int v_coloff = (lane >> 4) * 16;

    int kbs[3]; int nv = 0;
    for (int kb = b - 1; kb <= b + 1; kb++)
        if (kb >= 0 && kb < NB) kbs[nv++] = kb;

    // ---- preload: convert block 0 (fp16) into slot 0 ----
    {
        const int kb0 = kbs[0] * BS;
        const float4* kp = (const float4*)(Kg + (size_t)kb0 * DH);
        const float4* vp = (const float4*)(Vg + (size_t)kb0 * DH);
        #pragma unroll
        for (int f = 0; f < 8; f++) {
            const int idx = tid + f * 256;
            const uint32_t sw = SW128((uint32_t)(idx * 8));
            float4 kv = kp[idx];
            *(uint2*)(smem + 0 + sw) = make_uint2(pkh(kv.x, kv.y), pkh(kv.z, kv.w));
            float4 vv = vp[idx];
            *(uint2*)(smem + 16384 + sw) = make_uint2(pkh(vv.x, vv.y), pkh(vv.z, vv.w));
        }
        if (tid < BS) ((float*)(smem + OF_MSK))[tid] = Mr[kb0 + tid];
    }

    for (int i = 0; i < nv; i++) {
        __syncthreads();   // slot i%2 converts complete; slot (i+1)%2 free
        const int kb0  = kbs[i] * BS;
        const int slot = (i & 1) * SLOT_STRIDE;
        float* msk = (float*)(smem + OF_MSK + (i & 1) * 512);
        const bool more = (i + 1 < nv);
        const int nkb0  = more ? kbs[i + 1] * BS : 0;
        const int nslot = ((i + 1) & 1) * SLOT_STRIDE;

        #pragma unroll
        for (int h = 0; h < 2; h++) {      // two 64-key halves
            // ---- S = QhK + QlK (2-term), np-wise ----
            float s[8][4];
            #pragma unroll
            for (int ii = 0; ii < 8; ii++)
                #pragma unroll
                for (int j = 0; j < 4; j++) s[ii][j] = 0.f;

            #pragma unroll
            for (int ks = 0; ks < 4; ks++) {
                #pragma unroll
                for (int np = 0; np < 4; np++) {
                    const int keyrow = h * 64 + np * 16 + k_rowoff;
                    const uint32_t swo = SW128((uint32_t)(keyrow * 128 + ks * 32 + k_coloff));
                    uint32_t r[4];
                    ldsm_x4(r, sb + slot + swo);
                    mma_f16(s[2*np],   qh[ks], r);
                    mma_f16(s[2*np+1], qh[ks], r + 2);
                    mma_f16(s[2*np],   ql[ks], r);
                    mma_f16(s[2*np+1], ql[ks], r + 2);
                }
            }

            // ---- pipelined convert of NEXT block (K after h0, V+msk after h1) ----
            if (more) {
                if (h == 0) {
                    const float4* kp = (const float4*)(Kg + (size_t)nkb0 * DH);
                    #pragma unroll
                    for (int f = 0; f < 8; f++) {
                        const int idx = tid + f * 256;
                        const uint32_t sw = SW128((uint32_t)(idx * 8));
                        float4 kv = kp[idx];
                        *(uint2*)(smem + nslot + sw) =
                            make_uint2(pkh(kv.x, kv.y), pkh(kv.z, kv.w));
                    }
                } else {
                    const float4* vp = (const float4*)(Vg + (size_t)nkb0 * DH);
                    #pragma unroll
                    for (int f = 0; f < 8; f++) {
                        const int idx = tid + f * 256;
                        const uint32_t sw = SW128((uint32_t)(idx * 8));
                        float4 vv = vp[idx];
                        *(uint2*)(smem + nslot + 16384 + sw) =
                            make_uint2(pkh(vv.x, vv.y), pkh(vv.z, vv.w));
                    }
                    if (tid < BS)
                        ((float*)(smem + OF_MSK + ((i + 1) & 1) * 512))[tid] = Mr[nkb0 + tid];
                }
            }

            // ---- softmax (no-max) -> P split -> PV (2-term) ----
            #pragma unroll
            for (int kt = 0; kt < 4; kt++) {
                // stage V fragments (hide LDSM latency behind exp/pack)
                uint32_t VH[8][2];
                #pragma unroll
                for (int np = 0; np < 4; np++) {
                    const int vrow = h * 64 + kt * 16 + v_rowoff;
                    const uint32_t swo = SW128((uint32_t)(vrow * 128 + np * 32 + v_coloff));
                    uint32_t r[4];
                    ldsm_x4_t(r, sb + slot + 16384 + swo);
                    VH[2*np][0] = r[0]; VH[2*np][1] = r[1];
                    VH[2*np+1][0] = r[2]; VH[2*np+1][1] = r[3];
                }

                float e[2][4];
                #pragma unroll
                for (int u = 0; u < 2; u++) {
                    const int nt = 2 * kt + u;
                    #pragma unroll
                    for (int j = 0; j < 4; j++) {
                        const int col = h * 64 + nt * 8 + (lane & 3) * 2 + (j & 1);
                        float ev = __expf(fmaf(s[nt][j], 0.125f, msk[col]));
                        if (kb0 + col == 0) ev = 0.f;   // window never sees pos 0
                        e[u][j] = ev;
                        if (j < 2) lr0 += ev; else lr8 += ev;
                    }
                }
                uint32_t ph[4], pl[4];
                pksp16(e[0][0], e[0][1], ph[0], pl[0]);
                pksp16(e[0][2], e[0][3], ph[1], pl[1]);
                pksp16(e[1][0], e[1][1], ph[2], pl[2]);
                pksp16(e[1][2], e[1][3], ph[3], pl[3]);

                #pragma unroll
                for (int n2 = 0; n2 < 8; n2++) mma_f16(o[n2], ph, VH[n2]);
                #pragma unroll
                for (int n2 = 0; n2 < 8; n2++) mma_f16(o[n2], pl, VH[n2]);
            }
        }
    }

    // ---- epilogue: add global token, normalize, store ----
    lr0 += __shfl_xor_sync(0xffffffffu, lr0, 1);
    lr0 += __shfl_xor_sync(0xffffffffu, lr0, 2);
    lr8 += __shfl_xor_sync(0xffffffffu, lr8, 1);
    lr8 += __shfl_xor_sync(0xffffffffu, lr8, 2);
    const int r = lane >> 2;
    const float eg0 = egs[r0 + r];
    const float eg8 = egs[r0 + r + 8];
    const float il0 = 1.f / (lr0 + eg0);
    const float il8 = 1.f / (lr8 + eg8);
    #pragma unroll
    for (int n2 = 0; n2 < 8; n2++) {
        const int d = n2 * 8 + (lane & 3) * 2;
        float2 w0 = make_float2((o[n2][0] + eg0 * v0s[d])     * il0,
                                (o[n2][1] + eg0 * v0s[d + 1]) * il0);
        float2 w8 = make_float2((o[n2][2] + eg8 * v0s[d])     * il8,
                                (o[n2][3] + eg8 * v0s[d + 1]) * il8);
        *(float2*)(Og + (size_t)(r0 + r)     * DH + d) = w0;
        *(float2*)(Og + (size_t)(r0 + r + 8) * DH + d) = w8;
    }
}

// ============== row-0 full attention (split-K partials + reduce) ==========
__device__ float g_part[NBH][8][DH];
__device__ float g_plsum[NBH][8];

__global__ __launch_bounds__(256)
void row0_partial_kernel(const float* __restrict__ Q, const float* __restrict__ K,
                         const float* __restrict__ V, const float* __restrict__ M) {
    const int st = blockIdx.x;     // stripe of 512 keys
    const int bh = blockIdx.y;
    const int nIdx = bh / NH;
    const int tid = threadIdx.x;
    const int j0 = st * 512;

    __shared__ float q0[DH];
    __shared__ float esm[512];
    __shared__ float red[256];
    __shared__ float part[4][DH];

    const float* Qg = Q + (size_t)bh * TSEQ * DH;
    const float* Kg = K + (size_t)bh * TSEQ * DH;
    const float* Vg = V + (size_t)bh * TSEQ * DH;
    const float* Mr = M + (size_t)nIdx * TSEQ;

    if (tid < DH) q0[tid] = Qg[tid];
    __syncthreads();

    float l = 0.f;
    for (int j = tid; j < 512; j += 256) {
        const int pos = j0 + j;
        float dot = 0.f;
        const float4* kp = (const float4*)(Kg + (size_t)pos * DH);
        #pragma unroll
        for (int i = 0; i < 16; i++) {
            float4 kv = kp[i];
            dot += q0[4*i]*kv.x + q0[4*i+1]*kv.y + q0[4*i+2]*kv.z + q0[4*i+3]*kv.w;
        }
        float e = __expf(fmaf(dot, 0.125f, Mr[pos]));
        esm[j] = e;
        l += e;
    }
    red[tid] = l; __syncthreads();
    for (int s = 128; s > 0; s >>= 1) {
        if (tid < s) red[tid] += red[tid + s];
        __syncthreads();
    }
    if (tid == 0) g_plsum[bh][st] = red[0];

    const int dm = tid & 63, q = tid >> 6;
    float a = 0.f;
    for (int k = q * 128; k < q * 128 + 128; k++)
        a += esm[k] * Vg[(size_t)(j0 + k) * DH + dm];
    part[q][dm] = a;
    __syncthreads();
    if (tid < DH)
        g_part[bh][st][tid] = part[0][tid] + part[1][tid] + part[2][tid] + part[3][tid];
}

__global__ void row0_reduce_kernel(float* __restrict__ O) {
    const int bh = blockIdx.x;
    const int d = threadIdx.x;
    float s = 0.f, l = 0.f;
    #pragma unroll
    for (int st = 0; st < 8; st++) { s += g_part[bh][st][d]; l += g_plsum[bh][st]; }
    O[(size_t)bh * TSEQ * DH + d] = s / l;
}

// ================================ launch ===================================
extern "C" void kernel_launch(void* const* d_in, const int* in_sizes, int n_in,
                              void* d_out, int out_size) {
    const float* Q = (const float*)d_in[0];
    const float* K = (const float*)d_in[1];
    const float* V = (const float*)d_in[2];
    const float* M = (const float*)d_in[3];
    float* O = (float*)d_out;

    cudaFuncSetAttribute(attn_block_kernel,
                         cudaFuncAttributeMaxDynamicSharedMemorySize, SMEM_BYTES);
    dim3 grid(NB, NBH);
    attn_block_kernel<<<grid, 256, SMEM_BYTES>>>(Q, K, V, M, O);
    dim3 gridp(8, NBH);
    row0_partial_kernel<<<gridp, 256>>>(Q, K, V, M);
    row0_reduce_kernel<<<NBH, DH>>>(O);
}